// round 14
// baseline (speedup 1.0000x reference)
#include <cuda_runtime.h>
#include <cuda_bf16.h>
#include <cstdint>
#include <cstddef>

// ---------------------------------------------------------------------------
// CTLSTM: B=64, L=512, I=256, H=256, G=7H=1792
// Outputs: 6 planes, each (B, L+1, H) fp32, concatenated in d_out:
//   [h_decayed, h, c, c_bar, o, d]
//
// Scan topology: 128 CTAs = 8 pair-slices x 16 j-blocks. Each CTA hosts TWO
// independent 128-thread halves; half h runs batch-group (2*pair + h)
// (16 sorted groups of 4 batches). Halves share the SMEM weight slice but
// have private named barriers, flag domains, h tiles and reduction buffers,
// so one half's barrier latency is hidden under the other half's compute.
// ---------------------------------------------------------------------------

constexpr int Bb = 64;
constexpr int Ll = 512;
constexpr int Ii = 256;
constexpr int Hh = 256;
constexpr int Gg = 7 * Hh;                 // 1792
constexpr int NCTA = 128;
constexpr int NGRP = 16;                   // sorted batch groups
constexpr int GCTA = 16;                   // CTAs per group (j-blocks)
constexpr int BPG  = 4;                    // batches per group
constexpr int JPC  = 16;                   // j values per CTA
constexpr size_t S_OUT = (size_t)Bb * (Ll + 1) * Hh;   // 8,404,992

constexpr int WROW = 260;                  // padded row (16B aligned)

// Scan SMEM (floats): whs [7][16][WROW] + hs [2][4][WROW] + red [2][128][16]
constexpr int SM_WHS = 7 * JPC * WROW;             // 29120
constexpr int SM_HS  = SM_WHS;                     // + 2*4*WROW = 2080
constexpr int SM_RED = SM_WHS + 2 * BPG * WROW;    // 31200
constexpr int SCAN_SMEM = (SM_RED + 2 * 128 * 16) * 4;   // 141,184 B

// Device scratch (no allocation allowed)
__device__ float    g_xg[(size_t)Bb * Ll * Gg];   // 224 MB
__device__ float    g_h[2][Bb * Hh];              // h double buffer (RANK-indexed)
__device__ unsigned g_flag[NGRP][GCTA][32];       // per-CTA step flags (128B pad)
__device__ int      g_perm[Bb];                   // rank -> batch (desc seq_len)

typedef unsigned long long u64;

// ---------------------------------------------------------------------------
// Packed fp32x2 helpers
// ---------------------------------------------------------------------------
__device__ __forceinline__ u64 fma2(u64 a, u64 b, u64 c) {
    u64 d;
    asm("fma.rn.f32x2 %0, %1, %2, %3;" : "=l"(d) : "l"(a), "l"(b), "l"(c));
    return d;
}
__device__ __forceinline__ u64 dup2(float x) {
    u64 d;
    unsigned u = __float_as_uint(x);
    asm("mov.b64 %0, {%1, %2};" : "=l"(d) : "r"(u), "r"(u));
    return d;
}
__device__ __forceinline__ float lo2(u64 v) { return __uint_as_float((unsigned)v); }
__device__ __forceinline__ float hi2(u64 v) { return __uint_as_float((unsigned)(v >> 32)); }

// Release/acquire flag primitives
__device__ __forceinline__ void st_release(unsigned* p, unsigned v) {
    asm volatile("st.release.gpu.global.u32 [%0], %1;" :: "l"(p), "r"(v) : "memory");
}
__device__ __forceinline__ unsigned ld_acquire(const unsigned* p) {
    unsigned v;
    asm volatile("ld.acquire.gpu.global.u32 %0, [%1];" : "=r"(v) : "l"(p) : "memory");
    return v;
}

// Named barrier for one 128-thread half (ids 1 and 2; 0 stays __syncthreads)
__device__ __forceinline__ void barh(int half) {
    asm volatile("bar.sync %0, 128;" :: "r"(1 + half) : "memory");
}

// ---------------------------------------------------------------------------
// Fast transcendentals (error ~1e-6, far under the 1e-3 tolerance)
// ---------------------------------------------------------------------------
__device__ __forceinline__ float sigmoidf_(float x) {
    return __fdividef(1.0f, 1.0f + __expf(-x));
}
__device__ __forceinline__ float tanhf_(float x) {
    // tanh(x) = 1 - 2/(exp(2x)+1); symmetric form keeps error ~1e-7
    float e = __expf(-2.0f * fabsf(x));
    float r = 1.0f - __fdividef(2.0f * e, 1.0f + e);
    return copysignf(r, x);
}
__device__ __forceinline__ float softplusf_(float x) {
    return (x > 20.0f) ? x : log1pf(__expf(x));
}

// ---------------------------------------------------------------------------
// Init: zero flags, h0, t=0 output rows; compute seq-len rank permutation.
// ---------------------------------------------------------------------------
__global__ void init_kernel(float* __restrict__ out,
                            const int* __restrict__ seq_lens) {
    int i = blockIdx.x * blockDim.x + threadIdx.x;
    if (i < NGRP * GCTA * 32) ((unsigned*)g_flag)[i] = 0u;
    if (i < Bb * Hh) g_h[0][i] = 0.0f;
    if (i < Bb) {
        int my = __ldg(seq_lens + i);
        int rank = 0;
        for (int k = 0; k < Bb; ++k) {
            int lk = __ldg(seq_lens + k);
            rank += (lk > my) || (lk == my && k < i);
        }
        g_perm[rank] = i;
    }
    if (i < 6 * Bb * Hh) {
        int o = i / (Bb * Hh);
        int r = i % (Bb * Hh);
        int b = r >> 8;
        int j = r & 255;
        out[(size_t)o * S_OUT + (size_t)b * (Ll + 1) * Hh + j] = 0.0f;
    }
}

// ---------------------------------------------------------------------------
// Phase A GEMM with seq-len tile skip.
// ---------------------------------------------------------------------------
__global__ __launch_bounds__(256) void xg_gemm(const float* __restrict__ X,
                                               const float* __restrict__ W,
                                               const float* __restrict__ bx,
                                               const int* __restrict__ seq_lens) {
    const int m0 = blockIdx.y * 128;
    if ((m0 & 511) >= __ldg(seq_lens + (m0 >> 9))) return;

    __shared__ float As[2][16][128];
    __shared__ float Bs[2][16][128];

    const int tid = threadIdx.x;
    const int tx  = tid & 15;
    const int ty  = tid >> 4;
    const int n0  = blockIdx.x * 128;

    const int r0 = tid >> 2;
    const int r1 = r0 + 64;
    const int c4 = tid & 3;

    u64 acc2[8][4];
#pragma unroll
    for (int i = 0; i < 8; ++i)
#pragma unroll
        for (int j = 0; j < 4; ++j) acc2[i][j] = 0ull;

    const float4* Xr0 = (const float4*)(X + (size_t)(m0 + r0) * Ii);
    const float4* Xr1 = (const float4*)(X + (size_t)(m0 + r1) * Ii);
    const float4* Wr0 = (const float4*)(W + (size_t)(n0 + r0) * Ii);
    const float4* Wr1 = (const float4*)(W + (size_t)(n0 + r1) * Ii);

    {
        float4 v0 = __ldg(Xr0 + c4);
        float4 v1 = __ldg(Xr1 + c4);
        float4 w0 = __ldg(Wr0 + c4);
        float4 w1 = __ldg(Wr1 + c4);
        As[0][c4 * 4 + 0][r0] = v0.x; As[0][c4 * 4 + 1][r0] = v0.y;
        As[0][c4 * 4 + 2][r0] = v0.z; As[0][c4 * 4 + 3][r0] = v0.w;
        As[0][c4 * 4 + 0][r1] = v1.x; As[0][c4 * 4 + 1][r1] = v1.y;
        As[0][c4 * 4 + 2][r1] = v1.z; As[0][c4 * 4 + 3][r1] = v1.w;
        Bs[0][c4 * 4 + 0][r0] = w0.x; Bs[0][c4 * 4 + 1][r0] = w0.y;
        Bs[0][c4 * 4 + 2][r0] = w0.z; Bs[0][c4 * 4 + 3][r0] = w0.w;
        Bs[0][c4 * 4 + 0][r1] = w1.x; Bs[0][c4 * 4 + 1][r1] = w1.y;
        Bs[0][c4 * 4 + 2][r1] = w1.z; Bs[0][c4 * 4 + 3][r1] = w1.w;
    }
    __syncthreads();

    int buf = 0;
    for (int kt = 0; kt < 16; ++kt) {
        float4 pv0, pv1, pw0, pw1;
        if (kt < 15) {
            int f4 = (kt + 1) * 4 + c4;
            pv0 = __ldg(Xr0 + f4);
            pv1 = __ldg(Xr1 + f4);
            pw0 = __ldg(Wr0 + f4);
            pw1 = __ldg(Wr1 + f4);
        }
#pragma unroll
        for (int kk = 0; kk < 16; ++kk) {
            float4 a0 = *(const float4*)&As[buf][kk][ty * 8];
            float4 a1 = *(const float4*)&As[buf][kk][ty * 8 + 4];
            ulonglong2 bp0 = *(const ulonglong2*)&Bs[buf][kk][tx * 8];
            ulonglong2 bp1 = *(const ulonglong2*)&Bs[buf][kk][tx * 8 + 4];
            u64 bu[4] = {bp0.x, bp0.y, bp1.x, bp1.y};
            float av[8] = {a0.x, a0.y, a0.z, a0.w, a1.x, a1.y, a1.z, a1.w};
#pragma unroll
            for (int i = 0; i < 8; ++i) {
                u64 ad = dup2(av[i]);
#pragma unroll
                for (int j = 0; j < 4; ++j)
                    acc2[i][j] = fma2(ad, bu[j], acc2[i][j]);
            }
        }
        if (kt < 15) {
            int nb = buf ^ 1;
            As[nb][c4 * 4 + 0][r0] = pv0.x; As[nb][c4 * 4 + 1][r0] = pv0.y;
            As[nb][c4 * 4 + 2][r0] = pv0.z; As[nb][c4 * 4 + 3][r0] = pv0.w;
            As[nb][c4 * 4 + 0][r1] = pv1.x; As[nb][c4 * 4 + 1][r1] = pv1.y;
            As[nb][c4 * 4 + 2][r1] = pv1.z; As[nb][c4 * 4 + 3][r1] = pv1.w;
            Bs[nb][c4 * 4 + 0][r0] = pw0.x; Bs[nb][c4 * 4 + 1][r0] = pw0.y;
            Bs[nb][c4 * 4 + 2][r0] = pw0.z; Bs[nb][c4 * 4 + 3][r0] = pw0.w;
            Bs[nb][c4 * 4 + 0][r1] = pw1.x; Bs[nb][c4 * 4 + 1][r1] = pw1.y;
            Bs[nb][c4 * 4 + 2][r1] = pw1.z; Bs[nb][c4 * 4 + 3][r1] = pw1.w;
        }
        __syncthreads();
        buf ^= 1;
    }

    float bxr[8];
#pragma unroll
    for (int j = 0; j < 8; ++j) bxr[j] = __ldg(bx + n0 + tx * 8 + j);

#pragma unroll
    for (int i = 0; i < 8; ++i) {
        size_t row = (size_t)(m0 + ty * 8 + i);
        float4 o0, o1;
        o0.x = lo2(acc2[i][0]) + bxr[0]; o0.y = hi2(acc2[i][0]) + bxr[1];
        o0.z = lo2(acc2[i][1]) + bxr[2]; o0.w = hi2(acc2[i][1]) + bxr[3];
        o1.x = lo2(acc2[i][2]) + bxr[4]; o1.y = hi2(acc2[i][2]) + bxr[5];
        o1.z = lo2(acc2[i][3]) + bxr[6]; o1.w = hi2(acc2[i][3]) + bxr[7];
        float4* cp = (float4*)(g_xg + row * Gg + n0 + tx * 8);
        cp[0] = o0;
        cp[1] = o1;
    }
}

// ---------------------------------------------------------------------------
// Dual-half scan kernel.
// ---------------------------------------------------------------------------
__global__ __launch_bounds__(256, 1) void scan_kernel(
    const float* __restrict__ dt,
    const int*   __restrict__ seq_lens,
    const float* __restrict__ Wh,
    const float* __restrict__ bh,
    float*       __restrict__ out)
{
    extern __shared__ float smem[];
    float* whs = smem;                        // [7][16][WROW]  (shared by halves)
    float* hsA = smem + SM_HS;                // [2][4][WROW]   (per half)
    float* red = smem + SM_RED;               // [2][128][16]
    __shared__ int s_len[2][BPG];
    __shared__ int s_rb[2][BPG];

    const int tid   = threadIdx.x;
    const int pair  = blockIdx.x >> 4;        // 0..7
    const int jblk  = blockIdx.x & 15;        // 0..15
    const int j0    = jblk * JPC;
    const int half  = tid >> 7;               // 0 or 1
    const int tid_h = tid & 127;
    const int grp   = 2 * pair + half;        // 0..15 sorted group
    const int slot0 = grp * BPG;              // rank base

    const int kq   = tid_h >> 5;              // warp within half (k slice of 64)
    const int lane = tid_h & 31;
    const int bbl  = lane >> 4;               // batch-pair (0..1)
    const int ji   = lane & 15;               // j within block

    // Weights: shared, loaded by all 256 threads.
    for (int idx = tid; idx < 7 * JPC * 64; idx += 256) {
        int row = idx >> 6;
        int cf  = idx & 63;
        int g   = row >> 4;
        int jj  = row & 15;
        float4 v = __ldg((const float4*)(Wh + (size_t)(g * 256 + j0 + jj) * 256) + cf);
        *(float4*)(whs + row * WROW + cf * 4) = v;
    }

    if (tid_h < BPG) {
        int rb = __ldg(g_perm + slot0 + tid_h);
        s_rb[half][tid_h]  = rb;
        s_len[half][tid_h] = __ldg(seq_lens + rb);
    }
    __syncthreads();   // weights + lens visible to the whole CTA (barrier 0)

    int cta_max = 0;
#pragma unroll
    for (int i = 0; i < BPG; ++i) cta_max = max(cta_max, s_len[half][i]);

    // Readers: 64 per half (2 warps). Half A uses its even warps (SMSP 0,2),
    // half B its odd warps (SMSP 1,3) so reader tails don't collide.
    const bool isrd = ((kq & 1) == half);
    const int  r    = (kq >> 1) * 32 + lane;  // 0..63
    const int  bl   = r >> 4;                 // batch slot within group
    const int  jr   = r & 15;
    const int  slot = slot0 + bl;             // rank index for g_h
    const int  rb   = isrd ? s_rb[half][bl] : 0;
    const int  my_len = isrd ? s_len[half][bl] : 0;
    const int  rj   = j0 + jr;

    float bhr[7];
    if (isrd) {
#pragma unroll
        for (int g = 0; g < 7; ++g) bhr[g] = __ldg(bh + g * 256 + rj);
    }

    float* hsH   = hsA + half * (BPG * WROW);
    float* redH  = red + half * (128 * 16);
    const float* wbase = whs + ji * WROW;

    float cprev = 0.0f;

    for (int t = 0; t < cta_max; ++t) {
        const int cur = t & 1;
        const int nxt = cur ^ 1;

        // h tile load: 4 ranks x 256 = 256 float4 per half, 2 per thread.
        {
            const float4* src = (const float4*)(g_h[cur] + slot0 * Hh);
#pragma unroll
            for (int i = 0; i < 2; ++i) {
                int idx = tid_h + i * 128;        // 0..255
                int row = idx >> 6;
                int cf  = idx & 63;
                float4 v = __ldcg(src + idx);
                *(float4*)(hsH + row * WROW + cf * 4) = v;
            }
        }

        // xg + dt prefetch (readers), hidden under the dot.
        float xgv[7] = {0, 0, 0, 0, 0, 0, 0};
        float dtv = 0.0f;
        if (isrd && t < my_len) {
            const float* xp = g_xg + ((size_t)rb * Ll + t) * Gg + rj;
#pragma unroll
            for (int g = 0; g < 7; ++g) xgv[g] = __ldg(xp + g * 256);
            dtv = __ldg(dt + rb * Ll + t);
        }

        barh(half);   // hs visible within the half

        // Dot: thread covers batches {bbl*2, bbl*2+1}, j=ji, k=kq*64..+64.
        u64 acc2[7][2];
#pragma unroll
        for (int g = 0; g < 7; ++g) { acc2[g][0] = 0ull; acc2[g][1] = 0ull; }

        const float* hb0 = hsH + (bbl * 2 + 0) * WROW + kq * 64;
        const float* hb1 = hsH + (bbl * 2 + 1) * WROW + kq * 64;
        const float* wk  = wbase + kq * 64;
#pragma unroll
        for (int kc = 0; kc < 16; ++kc) {
            const int k = kc * 4;
            ulonglong2 hv0 = *(const ulonglong2*)(hb0 + k);
            ulonglong2 hv1 = *(const ulonglong2*)(hb1 + k);
#pragma unroll
            for (int g = 0; g < 7; ++g) {
                const ulonglong2 wv = *(const ulonglong2*)(wk + g * (JPC * WROW) + k);
                acc2[g][0] = fma2(hv0.x, wv.x, acc2[g][0]);
                acc2[g][0] = fma2(hv0.y, wv.y, acc2[g][0]);
                acc2[g][1] = fma2(hv1.x, wv.x, acc2[g][1]);
                acc2[g][1] = fma2(hv1.y, wv.y, acc2[g][1]);
            }
        }

        // Partials: 14 floats per thread (7 gates x 2 batches), stride 16.
        {
            float* rp = redH + tid_h * 16;
#pragma unroll
            for (int g = 0; g < 7; ++g) {
                rp[g]     = lo2(acc2[g][0]) + hi2(acc2[g][0]);
                rp[7 + g] = lo2(acc2[g][1]) + hi2(acc2[g][1]);
            }
        }
        barh(half);   // red visible

        float ht = 0.f, hfull = 0.f, cfull = 0.f, cb = 0.f, ov = 0.f, dv = 0.f;
        if (isrd) {
            float acc[7] = {0, 0, 0, 0, 0, 0, 0};
            const int wofs = (bl >> 1) * 16 + jr;   // writer (bbl, ji) slot
            const int bofs = (bl & 1) * 7;
#pragma unroll
            for (int q = 0; q < 4; ++q) {
                const float* rp = redH + (q * 32 + wofs) * 16 + bofs;
#pragma unroll
                for (int g = 0; g < 7; ++g) acc[g] += rp[g];
            }

            float iv  = sigmoidf_(acc[0] + xgv[0] + bhr[0]);
            float fv  = sigmoidf_(acc[1] + xgv[1] + bhr[1]);
            float zv  = tanhf_  (acc[2] + xgv[2] + bhr[2]);
            ov        = sigmoidf_(acc[3] + xgv[3] + bhr[3]);
            dv        = softplusf_(acc[4] + xgv[4] + bhr[4]);
            float ibv = sigmoidf_(acc[5] + xgv[5] + bhr[5]);
            float fbv = sigmoidf_(acc[6] + xgv[6] + bhr[6]);

            cfull = fv * cprev + iv * zv;
            hfull = ov * tanhf_(cfull);
            cb    = fbv * cprev + ibv * zv;
            float ct = cb + (cfull - cb) * __expf(-dv * dtv);
            ht    = ov * tanhf_(ct);

            if (t >= my_len) {
                ht = 0.0f; hfull = 0.0f; cfull = 0.0f; cb = 0.0f;
                ov = 0.0f; dv = 0.0f; ct = 0.0f;
            }
            __stcg(&g_h[nxt][slot * Hh + rj], ht);
            cprev = ct;
        }

        barh(half);                        // all h stores issued half-wide
        const bool dobar = (t < cta_max - 1);
        if (dobar && tid_h == 0) {
            __threadfence();               // order h stores before the release
            st_release(&g_flag[grp][jblk][0], (unsigned)(t + 1));
        }
        // Output stores (no cross-CTA consumer) overlap the poll.
        if (isrd) {
            const size_t base = (size_t)rb * ((Ll + 1) * Hh) + (size_t)(t + 1) * Hh + rj;
            out[0 * S_OUT + base] = ht;
            out[1 * S_OUT + base] = hfull;
            out[2 * S_OUT + base] = cfull;
            out[3 * S_OUT + base] = cb;
            out[4 * S_OUT + base] = ov;
            out[5 * S_OUT + base] = dv;
        }
        if (dobar && tid_h < GCTA) {
            while (ld_acquire(&g_flag[grp][tid_h][0]) < (unsigned)(t + 1)) {}
        }
        barh(half);                        // release half; hs safe to overwrite
    }

    // Tail: all batches of this group past seq_len — zero outputs.
    for (int t = cta_max; t < Ll; ++t) {
        if (isrd) {
            const size_t base = (size_t)rb * ((Ll + 1) * Hh) + (size_t)(t + 1) * Hh + rj;
#pragma unroll
            for (int p = 0; p < 6; ++p) out[p * S_OUT + base] = 0.0f;
        }
    }
}

// ---------------------------------------------------------------------------
// Launch
// ---------------------------------------------------------------------------
extern "C" void kernel_launch(void* const* d_in, const int* in_sizes, int n_in,
                              void* d_out, int out_size) {
    const float* x   = (const float*)d_in[0];
    const float* dt  = (const float*)d_in[1];
    const int*   sl  = (const int*)  d_in[2];
    const float* Wx  = (const float*)d_in[3];
    const float* bx  = (const float*)d_in[4];
    const float* Wh  = (const float*)d_in[5];
    const float* bh  = (const float*)d_in[6];
    float* out = (float*)d_out;

    cudaFuncSetAttribute(scan_kernel,
                         cudaFuncAttributeMaxDynamicSharedMemorySize, SCAN_SMEM);

    init_kernel<<<(6 * Bb * Hh + 255) / 256, 256>>>(out, sl);
    xg_gemm<<<dim3(Gg / 128, (Bb * Ll) / 128), 256>>>(x, Wx, bx, sl);
    scan_kernel<<<NCTA, 256, SCAN_SMEM>>>(dt, sl, Wh, bh, out);
}

// round 15
// speedup vs baseline: 1.2717x; 1.2717x over previous
#include <cuda_runtime.h>
#include <cuda_bf16.h>
#include <cstdint>
#include <cstddef>

// ---------------------------------------------------------------------------
// CTLSTM: B=64, L=512, I=256, H=256, G=7H=1792
// Outputs: 6 planes, each (B, L+1, H) fp32, concatenated in d_out:
//   [h_decayed, h, c, c_bar, o, d]
//
// Scan: 128 CTAs = 8 sorted batch-groups x 16 j-blocks (8 batches, 16 j per
// CTA). Dataflow sync: warp kq consumes h[j] only for j in [32kq,32kq+32),
// produced by CTAs jblk = 2kq,2kq+1 -> each warp polls just those 2 flags,
// gathers its h chunk from L2 into a private SMEM strip, and proceeds.
// ---------------------------------------------------------------------------

constexpr int Bb = 64;
constexpr int Ll = 512;
constexpr int Ii = 256;
constexpr int Hh = 256;
constexpr int Gg = 7 * Hh;                 // 1792
constexpr int NCTA = 128;
constexpr int NGRP = 8;                    // batch groups (sorted by seq_len)
constexpr int GCTA = 16;                   // CTAs per group (j-blocks)
constexpr int BPG  = 8;                    // batches per group
constexpr int JPC  = 16;                   // j values per CTA
constexpr size_t S_OUT = (size_t)Bb * (Ll + 1) * Hh;   // 8,404,992

constexpr int WROW = 260;                  // padded weight row (16B aligned)
constexpr int HROW = 36;                   // padded h row within a warp strip
constexpr int HWRP = BPG * HROW;           // 288 floats per warp strip
constexpr int RSTR = 34;                   // reduction stride

constexpr int SM_WHS = 7 * JPC * WROW;             // 29120
constexpr int SM_HW  = SM_WHS;                     // hw: 8 warps x 288
constexpr int SM_RED = SM_WHS + 8 * HWRP;          // 31424
constexpr int SCAN_SMEM = (SM_RED + 256 * RSTR) * 4;  // 160,512 B

// Device scratch (no allocation allowed)
__device__ float    g_xg[(size_t)Bb * Ll * Gg];   // 224 MB
__device__ float    g_h[2][Bb * Hh];              // h double buffer (RANK-indexed)
__device__ unsigned g_flag[NGRP][GCTA][32];       // per-CTA step flags (128B pad)
__device__ int      g_perm[Bb];                   // rank -> batch (desc seq_len)

typedef unsigned long long u64;

// ---------------------------------------------------------------------------
// Packed fp32x2 helpers
// ---------------------------------------------------------------------------
__device__ __forceinline__ u64 fma2(u64 a, u64 b, u64 c) {
    u64 d;
    asm("fma.rn.f32x2 %0, %1, %2, %3;" : "=l"(d) : "l"(a), "l"(b), "l"(c));
    return d;
}
__device__ __forceinline__ u64 dup2(float x) {
    u64 d;
    unsigned u = __float_as_uint(x);
    asm("mov.b64 %0, {%1, %2};" : "=l"(d) : "r"(u), "r"(u));
    return d;
}
__device__ __forceinline__ float lo2(u64 v) { return __uint_as_float((unsigned)v); }
__device__ __forceinline__ float hi2(u64 v) { return __uint_as_float((unsigned)(v >> 32)); }

// Release/acquire flag primitives
__device__ __forceinline__ void st_release(unsigned* p, unsigned v) {
    asm volatile("st.release.gpu.global.u32 [%0], %1;" :: "l"(p), "r"(v) : "memory");
}
__device__ __forceinline__ unsigned ld_acquire(const unsigned* p) {
    unsigned v;
    asm volatile("ld.acquire.gpu.global.u32 %0, [%1];" : "=r"(v) : "l"(p) : "memory");
    return v;
}

// ---------------------------------------------------------------------------
// Init: zero flags, h0, t=0 output rows; compute seq-len rank permutation.
// ---------------------------------------------------------------------------
__global__ void init_kernel(float* __restrict__ out,
                            const int* __restrict__ seq_lens) {
    int i = blockIdx.x * blockDim.x + threadIdx.x;
    if (i < NGRP * GCTA * 32) ((unsigned*)g_flag)[i] = 0u;
    if (i < Bb * Hh) g_h[0][i] = 0.0f;
    if (i < Bb) {
        int my = __ldg(seq_lens + i);
        int rank = 0;
        for (int k = 0; k < Bb; ++k) {
            int lk = __ldg(seq_lens + k);
            rank += (lk > my) || (lk == my && k < i);
        }
        g_perm[rank] = i;
    }
    if (i < 6 * Bb * Hh) {
        int o = i / (Bb * Hh);
        int r = i % (Bb * Hh);
        int b = r >> 8;
        int j = r & 255;
        out[(size_t)o * S_OUT + (size_t)b * (Ll + 1) * Hh + j] = 0.0f;
    }
}

// ---------------------------------------------------------------------------
// Phase A GEMM with seq-len tile skip.
// ---------------------------------------------------------------------------
__global__ __launch_bounds__(256) void xg_gemm(const float* __restrict__ X,
                                               const float* __restrict__ W,
                                               const float* __restrict__ bx,
                                               const int* __restrict__ seq_lens) {
    const int m0 = blockIdx.y * 128;
    if ((m0 & 511) >= __ldg(seq_lens + (m0 >> 9))) return;   // whole-CTA skip

    __shared__ float As[2][16][128];
    __shared__ float Bs[2][16][128];

    const int tid = threadIdx.x;
    const int tx  = tid & 15;
    const int ty  = tid >> 4;
    const int n0  = blockIdx.x * 128;

    const int r0 = tid >> 2;
    const int r1 = r0 + 64;
    const int c4 = tid & 3;

    u64 acc2[8][4];
#pragma unroll
    for (int i = 0; i < 8; ++i)
#pragma unroll
        for (int j = 0; j < 4; ++j) acc2[i][j] = 0ull;

    const float4* Xr0 = (const float4*)(X + (size_t)(m0 + r0) * Ii);
    const float4* Xr1 = (const float4*)(X + (size_t)(m0 + r1) * Ii);
    const float4* Wr0 = (const float4*)(W + (size_t)(n0 + r0) * Ii);
    const float4* Wr1 = (const float4*)(W + (size_t)(n0 + r1) * Ii);

    {
        float4 v0 = __ldg(Xr0 + c4);
        float4 v1 = __ldg(Xr1 + c4);
        float4 w0 = __ldg(Wr0 + c4);
        float4 w1 = __ldg(Wr1 + c4);
        As[0][c4 * 4 + 0][r0] = v0.x; As[0][c4 * 4 + 1][r0] = v0.y;
        As[0][c4 * 4 + 2][r0] = v0.z; As[0][c4 * 4 + 3][r0] = v0.w;
        As[0][c4 * 4 + 0][r1] = v1.x; As[0][c4 * 4 + 1][r1] = v1.y;
        As[0][c4 * 4 + 2][r1] = v1.z; As[0][c4 * 4 + 3][r1] = v1.w;
        Bs[0][c4 * 4 + 0][r0] = w0.x; Bs[0][c4 * 4 + 1][r0] = w0.y;
        Bs[0][c4 * 4 + 2][r0] = w0.z; Bs[0][c4 * 4 + 3][r0] = w0.w;
        Bs[0][c4 * 4 + 0][r1] = w1.x; Bs[0][c4 * 4 + 1][r1] = w1.y;
        Bs[0][c4 * 4 + 2][r1] = w1.z; Bs[0][c4 * 4 + 3][r1] = w1.w;
    }
    __syncthreads();

    int buf = 0;
    for (int kt = 0; kt < 16; ++kt) {
        float4 pv0, pv1, pw0, pw1;
        if (kt < 15) {
            int f4 = (kt + 1) * 4 + c4;
            pv0 = __ldg(Xr0 + f4);
            pv1 = __ldg(Xr1 + f4);
            pw0 = __ldg(Wr0 + f4);
            pw1 = __ldg(Wr1 + f4);
        }
#pragma unroll
        for (int kk = 0; kk < 16; ++kk) {
            float4 a0 = *(const float4*)&As[buf][kk][ty * 8];
            float4 a1 = *(const float4*)&As[buf][kk][ty * 8 + 4];
            ulonglong2 bp0 = *(const ulonglong2*)&Bs[buf][kk][tx * 8];
            ulonglong2 bp1 = *(const ulonglong2*)&Bs[buf][kk][tx * 8 + 4];
            u64 bu[4] = {bp0.x, bp0.y, bp1.x, bp1.y};
            float av[8] = {a0.x, a0.y, a0.z, a0.w, a1.x, a1.y, a1.z, a1.w};
#pragma unroll
            for (int i = 0; i < 8; ++i) {
                u64 ad = dup2(av[i]);
#pragma unroll
                for (int j = 0; j < 4; ++j)
                    acc2[i][j] = fma2(ad, bu[j], acc2[i][j]);
            }
        }
        if (kt < 15) {
            int nb = buf ^ 1;
            As[nb][c4 * 4 + 0][r0] = pv0.x; As[nb][c4 * 4 + 1][r0] = pv0.y;
            As[nb][c4 * 4 + 2][r0] = pv0.z; As[nb][c4 * 4 + 3][r0] = pv0.w;
            As[nb][c4 * 4 + 0][r1] = pv1.x; As[nb][c4 * 4 + 1][r1] = pv1.y;
            As[nb][c4 * 4 + 2][r1] = pv1.z; As[nb][c4 * 4 + 3][r1] = pv1.w;
            Bs[nb][c4 * 4 + 0][r0] = pw0.x; Bs[nb][c4 * 4 + 1][r0] = pw0.y;
            Bs[nb][c4 * 4 + 2][r0] = pw0.z; Bs[nb][c4 * 4 + 3][r0] = pw0.w;
            Bs[nb][c4 * 4 + 0][r1] = pw1.x; Bs[nb][c4 * 4 + 1][r1] = pw1.y;
            Bs[nb][c4 * 4 + 2][r1] = pw1.z; Bs[nb][c4 * 4 + 3][r1] = pw1.w;
        }
        __syncthreads();
        buf ^= 1;
    }

    float bxr[8];
#pragma unroll
    for (int j = 0; j < 8; ++j) bxr[j] = __ldg(bx + n0 + tx * 8 + j);

#pragma unroll
    for (int i = 0; i < 8; ++i) {
        size_t row = (size_t)(m0 + ty * 8 + i);
        float4 o0, o1;
        o0.x = lo2(acc2[i][0]) + bxr[0]; o0.y = hi2(acc2[i][0]) + bxr[1];
        o0.z = lo2(acc2[i][1]) + bxr[2]; o0.w = hi2(acc2[i][1]) + bxr[3];
        o1.x = lo2(acc2[i][2]) + bxr[4]; o1.y = hi2(acc2[i][2]) + bxr[5];
        o1.z = lo2(acc2[i][3]) + bxr[6]; o1.w = hi2(acc2[i][3]) + bxr[7];
        float4* cp = (float4*)(g_xg + row * Gg + n0 + tx * 8);
        cp[0] = o0;
        cp[1] = o1;
    }
}

// ---------------------------------------------------------------------------
// Scan helpers (R13-proven math)
// ---------------------------------------------------------------------------
__device__ __forceinline__ float sigmoidf_(float x) {
    return 1.0f / (1.0f + __expf(-x));
}
__device__ __forceinline__ float softplusf_(float x) {
    return (x > 20.0f) ? x : log1pf(__expf(x));
}

// ---------------------------------------------------------------------------
// Dataflow scan kernel.
// ---------------------------------------------------------------------------
__global__ __launch_bounds__(256, 1) void scan_kernel(
    const float* __restrict__ dt,
    const int*   __restrict__ seq_lens,
    const float* __restrict__ Wh,
    const float* __restrict__ bh,
    float*       __restrict__ out)
{
    extern __shared__ float smem[];
    float* whs = smem;                   // [7][16][WROW]
    float* hw  = smem + SM_HW;           // [8 warps][8 batches][HROW]
    float* red = smem + SM_RED;          // [256][RSTR]
    __shared__ int s_len[BPG];
    __shared__ int s_rb[BPG];

    const int tid  = threadIdx.x;
    const int grp  = blockIdx.x >> 4;
    const int jblk = blockIdx.x & 15;
    const int b0   = grp * BPG;          // rank base
    const int j0   = jblk * JPC;

    const int kq   = tid >> 5;           // warp = k slice of 32
    const int lane = tid & 31;
    const int bg   = lane >> 4;          // batch half (0..1)
    const int ji   = lane & 15;

    for (int idx = tid; idx < 7 * JPC * 64; idx += 256) {
        int row = idx >> 6;
        int cf  = idx & 63;
        int g   = row >> 4;
        int jj  = row & 15;
        float4 v = __ldg((const float4*)(Wh + (size_t)(g * 256 + j0 + jj) * 256) + cf);
        *(float4*)(whs + row * WROW + cf * 4) = v;
    }

    if (tid < BPG) {
        int rb = __ldg(g_perm + b0 + tid);
        s_rb[tid]  = rb;
        s_len[tid] = __ldg(seq_lens + rb);
    }
    __syncthreads();
    int cta_max = 0;
#pragma unroll
    for (int i = 0; i < BPG; ++i) cta_max = max(cta_max, s_len[i]);

    const bool isrd   = (tid < 128);
    const int  bl     = tid >> 4;        // slot within group (readers)
    const int  jr     = tid & 15;
    const int  rb     = isrd ? s_rb[bl] : 0;
    const int  rj     = j0 + jr;
    const int  my_len = isrd ? s_len[bl] : 0;

    float bhr[7];
    if (isrd) {
#pragma unroll
        for (int g = 0; g < 7; ++g) bhr[g] = __ldg(bh + g * 256 + rj);
    }

    // Per-warp pointers
    float*       hwm   = hw + kq * HWRP;                // this warp's h strip
    const float* hbase = hwm + bg * 4 * HROW;           // dot h base (local k)
    const float* wbase = whs + ji * WROW + kq * 32;     // dot weight base
    const unsigned* myflag = (lane < 2) ? &g_flag[grp][2 * kq + lane][0] : 0;

    float cprev = 0.0f;

    for (int t = 0; t < cta_max; ++t) {
        const int cur = t & 1;
        const int nxt = cur ^ 1;

        // xg + dt prefetch (readers) — independent of h, issue first.
        float xgv[7] = {0, 0, 0, 0, 0, 0, 0};
        float dtv = 0.0f;
        if (isrd && t < my_len) {
            const float* xp = g_xg + ((size_t)rb * Ll + t) * Gg + rj;
#pragma unroll
            for (int g = 0; g < 7; ++g) xgv[g] = __ldg(xp + g * 256);
            dtv = __ldg(dt + rb * Ll + t);
        }

        // Per-warp dataflow: wait only for this warp's 2 h-producers.
        if (t > 0 && lane < 2) {
            const unsigned tgt = (unsigned)t;
            while (ld_acquire(myflag) < tgt) {}
        }
        __syncwarp();

        // Gather this warp's h chunk: 8 ranks x 32 j (lane = local j).
        {
            const float* src = g_h[cur] + (b0 * Hh + kq * 32 + lane);
            float* dst = hwm + lane;
#pragma unroll
            for (int b = 0; b < BPG; ++b)
                dst[b * HROW] = __ldcg(src + b * Hh);
        }
        __syncwarp();

        // Dot: thread covers 4 batches (bg*4..+3), j=ji, k local 0..31.
        u64 acc2[7][4];
#pragma unroll
        for (int g = 0; g < 7; ++g)
#pragma unroll
            for (int bb = 0; bb < 4; ++bb) acc2[g][bb] = 0ull;

#pragma unroll
        for (int kc = 0; kc < 8; ++kc) {
            const int k = kc * 4;
            ulonglong2 hv[4];
#pragma unroll
            for (int bb = 0; bb < 4; ++bb)
                hv[bb] = *(const ulonglong2*)(hbase + bb * HROW + k);
#pragma unroll
            for (int g = 0; g < 7; ++g) {
                const ulonglong2 wv = *(const ulonglong2*)(wbase + g * (JPC * WROW) + k);
#pragma unroll
                for (int bb = 0; bb < 4; ++bb) {
                    acc2[g][bb] = fma2(hv[bb].x, wv.x, acc2[g][bb]);
                    acc2[g][bb] = fma2(hv[bb].y, wv.y, acc2[g][bb]);
                }
            }
        }

        {
            float vals[28];
#pragma unroll
            for (int bb = 0; bb < 4; ++bb)
#pragma unroll
                for (int g = 0; g < 7; ++g)
                    vals[bb * 7 + g] = lo2(acc2[g][bb]) + hi2(acc2[g][bb]);
            float2* rp2 = (float2*)(red + tid * RSTR);
#pragma unroll
            for (int k2 = 0; k2 < 14; ++k2)
                rp2[k2] = make_float2(vals[2 * k2], vals[2 * k2 + 1]);
        }
        __syncthreads();   // red visible (also: all warps done reading h[cur])

        float ht = 0.f, hfull = 0.f, cfull = 0.f, cb = 0.f, ov = 0.f, dv = 0.f;
        if (isrd) {
            const int rbg = bl >> 2;
            const int rbb = bl & 3;
            float acc[7] = {0, 0, 0, 0, 0, 0, 0};
#pragma unroll
            for (int q = 0; q < 8; ++q) {
                const float* rp = red + (q * 32 + rbg * 16 + jr) * RSTR + rbb * 7;
#pragma unroll
                for (int g = 0; g < 7; ++g) acc[g] += rp[g];
            }

            float iv  = sigmoidf_(acc[0] + xgv[0] + bhr[0]);
            float fv  = sigmoidf_(acc[1] + xgv[1] + bhr[1]);
            float zv  = tanhf   (acc[2] + xgv[2] + bhr[2]);
            ov        = sigmoidf_(acc[3] + xgv[3] + bhr[3]);
            dv        = softplusf_(acc[4] + xgv[4] + bhr[4]);
            float ibv = sigmoidf_(acc[5] + xgv[5] + bhr[5]);
            float fbv = sigmoidf_(acc[6] + xgv[6] + bhr[6]);

            cfull = fv * cprev + iv * zv;
            hfull = ov * tanhf(cfull);
            cb    = fbv * cprev + ibv * zv;
            float ct = cb + (cfull - cb) * __expf(-dv * dtv);
            ht    = ov * tanhf(ct);

            if (t >= my_len) {
                ht = 0.0f; hfull = 0.0f; cfull = 0.0f; cb = 0.0f;
                ov = 0.0f; dv = 0.0f; ct = 0.0f;
            }
            __stcg(&g_h[nxt][(b0 + bl) * Hh + rj], ht);   // rank-indexed
            cprev = ct;
        }

        __syncthreads();                  // all h stores issued CTA-wide
        if (t < cta_max - 1 && tid == 0) {
            __threadfence();              // order h stores before the release
            st_release(&g_flag[grp][jblk][0], (unsigned)(t + 1));
        }
        // Output stores have no cross-CTA consumer: issue after the release.
        if (isrd) {
            const size_t base = (size_t)rb * ((Ll + 1) * Hh) + (size_t)(t + 1) * Hh + rj;
            out[0 * S_OUT + base] = ht;
            out[1 * S_OUT + base] = hfull;
            out[2 * S_OUT + base] = cfull;
            out[3 * S_OUT + base] = cb;
            out[4 * S_OUT + base] = ov;
            out[5 * S_OUT + base] = dv;
        }
    }

    // Tail: every batch in this group is past its seq_len — zero outputs.
    for (int t = cta_max; t < Ll; ++t) {
        if (isrd) {
            const size_t base = (size_t)rb * ((Ll + 1) * Hh) + (size_t)(t + 1) * Hh + rj;
#pragma unroll
            for (int p = 0; p < 6; ++p) out[p * S_OUT + base] = 0.0f;
        }
    }
}

// ---------------------------------------------------------------------------
// Launch
// ---------------------------------------------------------------------------
extern "C" void kernel_launch(void* const* d_in, const int* in_sizes, int n_in,
                              void* d_out, int out_size) {
    const float* x   = (const float*)d_in[0];
    const float* dt  = (const float*)d_in[1];
    const int*   sl  = (const int*)  d_in[2];
    const float* Wx  = (const float*)d_in[3];
    const float* bx  = (const float*)d_in[4];
    const float* Wh  = (const float*)d_in[5];
    const float* bh  = (const float*)d_in[6];
    float* out = (float*)d_out;

    cudaFuncSetAttribute(scan_kernel,
                         cudaFuncAttributeMaxDynamicSharedMemorySize, SCAN_SMEM);

    init_kernel<<<(6 * Bb * Hh + 255) / 256, 256>>>(out, sl);
    xg_gemm<<<dim3(Gg / 128, (Bb * Ll) / 128), 256>>>(x, Wx, bx, sl);
    scan_kernel<<<NCTA, 256, SCAN_SMEM>>>(dt, sl, Wh, bh, out);
}